// round 13
// baseline (speedup 1.0000x reference)
#include <cuda_runtime.h>
#include <cuda_fp16.h>
#include <cstdint>

#define EPSF 1e-8f
#define COLS 8192
#define BS 64
#define NB 128          // quant-blocks per row
#define NCELL 512       // LUT cells over x_norm in [-1,1)
#define NTHREADS 256

typedef unsigned int u32;

// One CTA per row (8192 floats). Mapping (R10, proven): 8 lanes per block.
// Warp w, iter i (0..3): group g = lane>>3 owns block qb = 16w + 4i + g.
// Thread k = lane&7 holds elems [k*4,k*4+4) and [32+k*4,...) of its block.
//
// R13 delta vs R12: BRANCHLESS straddle handling. lutm[ic] is loaded
// unconditionally (-1e30 sentinel for non-straddle cells makes the select
// degenerate there). Removes the 62%-taken divergent branch (BSSY/BSYNC +
// predicated tail) that pushed alu to 40%. One extra 4B LDS per element,
// paid from L1's ~50% headroom.
__global__ __launch_bounds__(NTHREADS, 5)
void nf4_kernel(const float* __restrict__ x, float* __restrict__ out)
{
    __shared__ u32   lutv[NCELL + 1];   // packed {t_hi, t_lo} fp16 pair
    __shared__ float lutm[NCELL + 1];   // fp32 midpoint (-1e30 if no straddle)
    __shared__ float2 qc[NB];           // {a, b} per quant-block
    __shared__ float scale_s[NB];
    __shared__ float bmin_s[NB];
    __shared__ float t_s[16];
    __shared__ float m_s[15];           // midpoints, in 512-cell coordinates
    __shared__ float sm_smin, sm_smax;

    const int tid  = threadIdx.x;
    const int lane = tid & 31;
    const int warp = tid >> 5;
    const int g    = lane >> 3;         // 8-lane group (0..3)
    const int k    = lane & 7;          // sub-lane in group
    const long long row_base = (long long)blockIdx.x * COLS;

    // ---- phase 0: NF4 table (ndtri at midpoints, normalized, fp16-rounded) ----
    if (tid < 16) {
        // ndtri(p) = sqrt(2)*erfinv(2p-1); sqrt(2) cancels in max-abs norm.
        float p   = (2.0f * ((float)tid + 0.5f)) / 16.0f - 1.0f;
        float q   = erfinvf(p);
        float q0  = erfinvf(2.0f * 0.5f  / 16.0f - 1.0f);
        float q15 = erfinvf(2.0f * 15.5f / 16.0f - 1.0f);
        float qmax = fmaxf(fabsf(q0), fabsf(q15));
        t_s[tid] = __half2float(__float2half(q / qmax));
    }
    __syncthreads();
    if (tid < 15) {
        // boundary between level tid and tid+1 in 512-cell coords:
        // cell(x_norm) = (x_norm + 1) * 256
        m_s[tid] = ((t_s[tid] + t_s[tid + 1]) * 0.5f + 1.0f) * 256.0f;
    }
    __syncthreads();

    // ---- phase 0b: range LUT, cell c covers fcell in [c, c+1) (truncation
    // indexing). Min midpoint gap ~21.6 cells -> each cell straddles at most
    // one boundary. Strict '>' matches argmin's first-index tie rule.
    for (int c = tid; c <= NCELL; c += NTHREADS) {
        int jlo = 0, jhi = 0;
        float fc = (float)c;
        #pragma unroll
        for (int kk = 0; kk < 15; kk++) {
            jlo += (m_s[kk] < fc)        ? 1 : 0;
            jhi += (m_s[kk] < fc + 1.0f) ? 1 : 0;
        }
        u32 tlo = (u32)__half_as_ushort(__float2half(t_s[jlo]));
        u32 thi;
        float mid;
        if (jhi > jlo) { thi = (u32)__half_as_ushort(__float2half(t_s[jlo + 1])); mid = m_s[jlo]; }
        else           { thi = tlo;                                               mid = -1e30f;   }
        lutv[c] = (thi << 16) | tlo;
        lutm[c] = mid;
    }
    __syncthreads();   // LUT ready before phase-1 quantize

    // ---- phase 1: 4 iterations; each: one block per 8-lane group ----
    u32 stash[16];                      // 4 iters x 8 elems -> 4 packed half2
    #pragma unroll
    for (int i = 0; i < 4; i++) {
        const int qb    = warp * 16 + i * 4 + g;
        const int ebase = qb * BS + k * 4;
        float4 v0 = __ldcs(reinterpret_cast<const float4*>(x + row_base + ebase));
        float4 v1 = __ldcs(reinterpret_cast<const float4*>(x + row_base + ebase + 32));

        // 8-elem in-register tree
        float mn = fminf(fminf(fminf(v0.x, v0.y), fminf(v0.z, v0.w)),
                         fminf(fminf(v1.x, v1.y), fminf(v1.z, v1.w)));
        float mx = fmaxf(fmaxf(fmaxf(v0.x, v0.y), fmaxf(v0.z, v0.w)),
                         fmaxf(fmaxf(v1.x, v1.y), fmaxf(v1.z, v1.w)));
        // 3-level butterfly within the 8-lane group
        mn = fminf(mn, __shfl_xor_sync(0xffffffffu, mn, 1));
        mx = fmaxf(mx, __shfl_xor_sync(0xffffffffu, mx, 1));
        mn = fminf(mn, __shfl_xor_sync(0xffffffffu, mn, 2));
        mx = fmaxf(mx, __shfl_xor_sync(0xffffffffu, mx, 2));
        mn = fminf(mn, __shfl_xor_sync(0xffffffffu, mn, 4));
        mx = fmaxf(mx, __shfl_xor_sync(0xffffffffu, mx, 4));

        float scale = mx - mn;          // exact fp32 subtract, as reference
        if (k == 0) { bmin_s[qb] = mn; scale_s[qb] = scale; }

        // cell(x) = 512*(x - mn)/(scale + eps) = x*s1 + s2
        float s1 = __fdividef(512.0f, scale + EPSF);   // MUFU.RCP + FMUL
        float s2 = -mn * s1;
        float vr[8];
        *reinterpret_cast<float4*>(vr)     = v0;
        *reinterpret_cast<float4*>(vr + 4) = v1;
        #pragma unroll
        for (int j = 0; j < 8; j++) {
            float fcell = fmaf(vr[j], s1, s2);
            int ic = (int)fcell;        // trunc clamps tiny negatives to 0
            u32   tt  = lutv[ic];       // 4B gather
            float mid = lutm[ic];       // 4B gather (sentinel -1e30 if none)
            u32 t16 = (fcell > mid) ? (tt >> 16) : (tt & 0xffffu);
            if ((j & 1) == 0) stash[i * 4 + (j >> 1)]  = t16;
            else              stash[i * 4 + (j >> 1)] |= t16 << 16;
        }
    }
    __syncthreads();

    // ---- phase 2: row-level min/max of the 128 block scales ----
    if (warp == 0) {
        float a0 = scale_s[lane];
        float a1 = scale_s[lane + 32];
        float a2 = scale_s[lane + 64];
        float a3 = scale_s[lane + 96];
        float mn = fminf(fminf(a0, a1), fminf(a2, a3));
        float mx = fmaxf(fmaxf(a0, a1), fmaxf(a2, a3));
        #pragma unroll
        for (int o = 16; o >= 1; o >>= 1) {
            mn = fminf(mn, __shfl_xor_sync(0xffffffffu, mn, o));
            mx = fmaxf(mx, __shfl_xor_sync(0xffffffffu, mx, o));
        }
        if (lane == 0) { sm_smin = mn; sm_smax = mx; }
    }
    __syncthreads();

    // ---- phase 3: per-block output constants ----
    if (tid < NB) {
        float smin  = sm_smin, smax = sm_smax;
        float scale = scale_s[tid];
        float bmin  = bmin_s[tid];
        float d     = smax - smin;
        // double quantization of scale (8-bit, round-half-even = rintf)
        float sq    = rintf((scale - smin) / (d + EPSF) * 255.0f);
        float srec  = smin + sq / 255.0f * d;
        // out = (t+1)/2 * srec + bmin == t*a + b
        float a = srec * 0.5f;
        float b = a + bmin;
        qc[tid] = make_float2(a, b);
    }
    __syncthreads();

    // ---- phase 4: dequant from register stash, coalesced streaming store ----
    #pragma unroll
    for (int i = 0; i < 4; i++) {
        const int qb    = warp * 16 + i * 4 + g;
        const int ebase = qb * BS + k * 4;
        float2 ab = qc[qb];
        u32 w0 = stash[i * 4 + 0];
        u32 w1 = stash[i * 4 + 1];
        u32 w2 = stash[i * 4 + 2];
        u32 w3 = stash[i * 4 + 3];
        __half2 h0 = *reinterpret_cast<__half2*>(&w0);
        __half2 h1 = *reinterpret_cast<__half2*>(&w1);
        __half2 h2 = *reinterpret_cast<__half2*>(&w2);
        __half2 h3 = *reinterpret_cast<__half2*>(&w3);
        float4 o0, o1;
        o0.x = fmaf(__low2float(h0),  ab.x, ab.y);
        o0.y = fmaf(__high2float(h0), ab.x, ab.y);
        o0.z = fmaf(__low2float(h1),  ab.x, ab.y);
        o0.w = fmaf(__high2float(h1), ab.x, ab.y);
        o1.x = fmaf(__low2float(h2),  ab.x, ab.y);
        o1.y = fmaf(__high2float(h2), ab.x, ab.y);
        o1.z = fmaf(__low2float(h3),  ab.x, ab.y);
        o1.w = fmaf(__high2float(h3), ab.x, ab.y);
        __stcs(reinterpret_cast<float4*>(out + row_base + ebase),      o0);
        __stcs(reinterpret_cast<float4*>(out + row_base + ebase + 32), o1);
    }
}

extern "C" void kernel_launch(void* const* d_in, const int* in_sizes, int n_in,
                              void* d_out, int out_size)
{
    const float* x = (const float*)d_in[0];
    float* out = (float*)d_out;
    int rows = in_sizes[0] / COLS;   // 2048
    nf4_kernel<<<rows, NTHREADS>>>(x, out);
}

// round 14
// speedup vs baseline: 1.0621x; 1.0621x over previous
#include <cuda_runtime.h>
#include <cuda_fp16.h>
#include <cstdint>

#define EPSF 1e-8f
#define COLS 8192
#define BS 64
#define NB 128          // quant-blocks per row
#define NCELL 512       // LUT cells over x_norm in [-1,1)
#define NTHREADS 256

typedef unsigned int u32;

// One CTA per row (8192 floats). Mapping (R10, proven): 8 lanes per block.
// Warp w, iter i (0..3): group g = lane>>3 owns block qb = 16w + 4i + g.
// Thread k = lane&7 holds elems [k*4,k*4+4) and [32+k*4,...) of its block.
//
// R14: single 8B LUT entry {midpoint_f32, packed half2(t_lo,t_hi)} at
// NCELL=512 + BRANCHLESS select. One LDS.64 gather per element (same gather
// count as R12's branch, half of R13's), zero branch machinery
// (R10 measured this select at alu=24.7%). occ=5, ldcs/stcs kept.
__global__ __launch_bounds__(NTHREADS, 5)
void nf4_kernel(const float* __restrict__ x, float* __restrict__ out)
{
    __shared__ float2 lut[NCELL + 1];   // {midpoint (-1e30 sentinel), bits(half2)}
    __shared__ float2 qc[NB];           // {a, b} per quant-block
    __shared__ float scale_s[NB];
    __shared__ float bmin_s[NB];
    __shared__ float t_s[16];
    __shared__ float m_s[15];           // midpoints, in 512-cell coordinates
    __shared__ float sm_smin, sm_smax;

    const int tid  = threadIdx.x;
    const int lane = tid & 31;
    const int warp = tid >> 5;
    const int g    = lane >> 3;         // 8-lane group (0..3)
    const int k    = lane & 7;          // sub-lane in group
    const long long row_base = (long long)blockIdx.x * COLS;

    // ---- phase 0: NF4 table (ndtri at midpoints, normalized, fp16-rounded) ----
    if (tid < 16) {
        // ndtri(p) = sqrt(2)*erfinv(2p-1); sqrt(2) cancels in max-abs norm.
        float p   = (2.0f * ((float)tid + 0.5f)) / 16.0f - 1.0f;
        float q   = erfinvf(p);
        float q0  = erfinvf(2.0f * 0.5f  / 16.0f - 1.0f);
        float q15 = erfinvf(2.0f * 15.5f / 16.0f - 1.0f);
        float qmax = fmaxf(fabsf(q0), fabsf(q15));
        t_s[tid] = __half2float(__float2half(q / qmax));
    }
    __syncthreads();
    if (tid < 15) {
        // boundary between level tid and tid+1 in 512-cell coords:
        // cell(x_norm) = (x_norm + 1) * 256
        m_s[tid] = ((t_s[tid] + t_s[tid + 1]) * 0.5f + 1.0f) * 256.0f;
    }
    __syncthreads();

    // ---- phase 0b: range LUT, cell c covers fcell in [c, c+1) (truncation
    // indexing). Min midpoint gap ~21.6 cells -> each cell straddles at most
    // one boundary. Strict '>' matches argmin's first-index tie rule.
    for (int c = tid; c <= NCELL; c += NTHREADS) {
        int jlo = 0, jhi = 0;
        float fc = (float)c;
        #pragma unroll
        for (int kk = 0; kk < 15; kk++) {
            jlo += (m_s[kk] < fc)        ? 1 : 0;
            jhi += (m_s[kk] < fc + 1.0f) ? 1 : 0;
        }
        u32 tlo = (u32)__half_as_ushort(__float2half(t_s[jlo]));
        u32 thi;
        float mid;
        if (jhi > jlo) { thi = (u32)__half_as_ushort(__float2half(t_s[jlo + 1])); mid = m_s[jlo]; }
        else           { thi = tlo;                                               mid = -1e30f;   }
        float2 e;
        e.x = mid;
        e.y = __uint_as_float((thi << 16) | tlo);
        lut[c] = e;
    }
    __syncthreads();   // LUT ready before phase-1 quantize

    // ---- phase 1: 4 iterations; each: one block per 8-lane group ----
    u32 stash[16];                      // 4 iters x 8 elems -> 4 packed half2
    #pragma unroll
    for (int i = 0; i < 4; i++) {
        const int qb    = warp * 16 + i * 4 + g;
        const int ebase = qb * BS + k * 4;
        float4 v0 = __ldcs(reinterpret_cast<const float4*>(x + row_base + ebase));
        float4 v1 = __ldcs(reinterpret_cast<const float4*>(x + row_base + ebase + 32));

        // 8-elem in-register tree
        float mn = fminf(fminf(fminf(v0.x, v0.y), fminf(v0.z, v0.w)),
                         fminf(fminf(v1.x, v1.y), fminf(v1.z, v1.w)));
        float mx = fmaxf(fmaxf(fmaxf(v0.x, v0.y), fmaxf(v0.z, v0.w)),
                         fmaxf(fmaxf(v1.x, v1.y), fmaxf(v1.z, v1.w)));
        // 3-level butterfly within the 8-lane group
        mn = fminf(mn, __shfl_xor_sync(0xffffffffu, mn, 1));
        mx = fmaxf(mx, __shfl_xor_sync(0xffffffffu, mx, 1));
        mn = fminf(mn, __shfl_xor_sync(0xffffffffu, mn, 2));
        mx = fmaxf(mx, __shfl_xor_sync(0xffffffffu, mx, 2));
        mn = fminf(mn, __shfl_xor_sync(0xffffffffu, mn, 4));
        mx = fmaxf(mx, __shfl_xor_sync(0xffffffffu, mx, 4));

        float scale = mx - mn;          // exact fp32 subtract, as reference
        if (k == 0) { bmin_s[qb] = mn; scale_s[qb] = scale; }

        // cell(x) = 512*(x - mn)/(scale + eps) = x*s1 + s2
        float s1 = __fdividef(512.0f, scale + EPSF);   // MUFU.RCP + FMUL
        float s2 = -mn * s1;
        float vr[8];
        *reinterpret_cast<float4*>(vr)     = v0;
        *reinterpret_cast<float4*>(vr + 4) = v1;
        #pragma unroll
        for (int j = 0; j < 8; j++) {
            float fcell = fmaf(vr[j], s1, s2);
            int ic = (int)fcell;        // trunc clamps tiny negatives to 0
            float2 L = lut[ic];         // ONE LDS.64 gather
            u32 tt = __float_as_uint(L.y);
            u32 t16 = (fcell > L.x) ? (tt >> 16) : (tt & 0xffffu);
            if ((j & 1) == 0) stash[i * 4 + (j >> 1)]  = t16;
            else              stash[i * 4 + (j >> 1)] |= t16 << 16;
        }
    }
    __syncthreads();

    // ---- phase 2: row-level min/max of the 128 block scales ----
    if (warp == 0) {
        float a0 = scale_s[lane];
        float a1 = scale_s[lane + 32];
        float a2 = scale_s[lane + 64];
        float a3 = scale_s[lane + 96];
        float mn = fminf(fminf(a0, a1), fminf(a2, a3));
        float mx = fmaxf(fmaxf(a0, a1), fmaxf(a2, a3));
        #pragma unroll
        for (int o = 16; o >= 1; o >>= 1) {
            mn = fminf(mn, __shfl_xor_sync(0xffffffffu, mn, o));
            mx = fmaxf(mx, __shfl_xor_sync(0xffffffffu, mx, o));
        }
        if (lane == 0) { sm_smin = mn; sm_smax = mx; }
    }
    __syncthreads();

    // ---- phase 3: per-block output constants ----
    if (tid < NB) {
        float smin  = sm_smin, smax = sm_smax;
        float scale = scale_s[tid];
        float bmin  = bmin_s[tid];
        float d     = smax - smin;
        // double quantization of scale (8-bit, round-half-even = rintf)
        float sq    = rintf((scale - smin) / (d + EPSF) * 255.0f);
        float srec  = smin + sq / 255.0f * d;
        // out = (t+1)/2 * srec + bmin == t*a + b
        float a = srec * 0.5f;
        float b = a + bmin;
        qc[tid] = make_float2(a, b);
    }
    __syncthreads();

    // ---- phase 4: dequant from register stash, coalesced streaming store ----
    #pragma unroll
    for (int i = 0; i < 4; i++) {
        const int qb    = warp * 16 + i * 4 + g;
        const int ebase = qb * BS + k * 4;
        float2 ab = qc[qb];
        u32 w0 = stash[i * 4 + 0];
        u32 w1 = stash[i * 4 + 1];
        u32 w2 = stash[i * 4 + 2];
        u32 w3 = stash[i * 4 + 3];
        __half2 h0 = *reinterpret_cast<__half2*>(&w0);
        __half2 h1 = *reinterpret_cast<__half2*>(&w1);
        __half2 h2 = *reinterpret_cast<__half2*>(&w2);
        __half2 h3 = *reinterpret_cast<__half2*>(&w3);
        float4 o0, o1;
        o0.x = fmaf(__low2float(h0),  ab.x, ab.y);
        o0.y = fmaf(__high2float(h0), ab.x, ab.y);
        o0.z = fmaf(__low2float(h1),  ab.x, ab.y);
        o0.w = fmaf(__high2float(h1), ab.x, ab.y);
        o1.x = fmaf(__low2float(h2),  ab.x, ab.y);
        o1.y = fmaf(__high2float(h2), ab.x, ab.y);
        o1.z = fmaf(__low2float(h3),  ab.x, ab.y);
        o1.w = fmaf(__high2float(h3), ab.x, ab.y);
        __stcs(reinterpret_cast<float4*>(out + row_base + ebase),      o0);
        __stcs(reinterpret_cast<float4*>(out + row_base + ebase + 32), o1);
    }
}

extern "C" void kernel_launch(void* const* d_in, const int* in_sizes, int n_in,
                              void* d_out, int out_size)
{
    const float* x = (const float*)d_in[0];
    float* out = (float*)d_out;
    int rows = in_sizes[0] / COLS;   // 2048
    nf4_kernel<<<rows, NTHREADS>>>(x, out);
}

// round 15
// speedup vs baseline: 1.0734x; 1.0106x over previous
#include <cuda_runtime.h>
#include <cuda_fp16.h>
#include <cstdint>

#define EPSF 1e-8f
#define COLS 8192
#define BS 64
#define NB 128          // quant-blocks per row
#define NCELL 512       // LUT cells over x_norm in [-1,1)
#define NTHREADS 256

typedef unsigned int u32;

// One CTA per row (8192 floats). Mapping (R10, proven): 8 lanes per block.
// Warp w, iter i (0..3): group g = lane>>3 owns block qb = 16w + 4i + g.
// Thread k = lane&7 holds elems [k*4,k*4+4) and [32+k*4,...) of its block.
//
// R15 = R12 (measured best: LDS.32 lutv gather + RARE lutm access) with two
// ALU shavings that add zero wavefronts:
//  - straddle midpoint via conditional EXPRESSION -> @P LDS + FSEL
//    (no BSSY/BSYNC, predicated-off lanes cost no wavefronts)
//  - pair packing via one PRMT (__byte_perm) instead of SHL+OR
__global__ __launch_bounds__(NTHREADS, 5)
void nf4_kernel(const float* __restrict__ x, float* __restrict__ out)
{
    __shared__ u32   lutv[NCELL + 1];   // packed {t_hi, t_lo} fp16 pair
    __shared__ float lutm[NCELL + 1];   // fp32 midpoint (straddle cells only)
    __shared__ float2 qc[NB];           // {a, b} per quant-block
    __shared__ float scale_s[NB];
    __shared__ float bmin_s[NB];
    __shared__ float t_s[16];
    __shared__ float m_s[15];           // midpoints, in 512-cell coordinates
    __shared__ float sm_smin, sm_smax;

    const int tid  = threadIdx.x;
    const int lane = tid & 31;
    const int warp = tid >> 5;
    const int g    = lane >> 3;         // 8-lane group (0..3)
    const int k    = lane & 7;          // sub-lane in group
    const long long row_base = (long long)blockIdx.x * COLS;

    // ---- phase 0: NF4 table (ndtri at midpoints, normalized, fp16-rounded) ----
    if (tid < 16) {
        // ndtri(p) = sqrt(2)*erfinv(2p-1); sqrt(2) cancels in max-abs norm.
        float p   = (2.0f * ((float)tid + 0.5f)) / 16.0f - 1.0f;
        float q   = erfinvf(p);
        float q0  = erfinvf(2.0f * 0.5f  / 16.0f - 1.0f);
        float q15 = erfinvf(2.0f * 15.5f / 16.0f - 1.0f);
        float qmax = fmaxf(fabsf(q0), fabsf(q15));
        t_s[tid] = __half2float(__float2half(q / qmax));
    }
    __syncthreads();
    if (tid < 15) {
        // boundary between level tid and tid+1 in 512-cell coords:
        // cell(x_norm) = (x_norm + 1) * 256
        m_s[tid] = ((t_s[tid] + t_s[tid + 1]) * 0.5f + 1.0f) * 256.0f;
    }
    __syncthreads();

    // ---- phase 0b: range LUT, cell c covers fcell in [c, c+1) (truncation
    // indexing). Min midpoint gap ~21.6 cells -> each cell straddles at most
    // one boundary. Strict '>' matches argmin's first-index tie rule.
    for (int c = tid; c <= NCELL; c += NTHREADS) {
        int jlo = 0, jhi = 0;
        float fc = (float)c;
        #pragma unroll
        for (int kk = 0; kk < 15; kk++) {
            jlo += (m_s[kk] < fc)        ? 1 : 0;
            jhi += (m_s[kk] < fc + 1.0f) ? 1 : 0;
        }
        u32 tlo = (u32)__half_as_ushort(__float2half(t_s[jlo]));
        u32 thi;
        float mid;
        if (jhi > jlo) { thi = (u32)__half_as_ushort(__float2half(t_s[jlo + 1])); mid = m_s[jlo]; }
        else           { thi = tlo;                                               mid = -1e30f;   }
        lutv[c] = (thi << 16) | tlo;
        lutm[c] = mid;
    }
    __syncthreads();   // LUT ready before phase-1 quantize

    // ---- phase 1: 4 iterations; each: one block per 8-lane group ----
    u32 stash[16];                      // 4 iters x 8 elems -> 4 packed half2
    #pragma unroll
    for (int i = 0; i < 4; i++) {
        const int qb    = warp * 16 + i * 4 + g;
        const int ebase = qb * BS + k * 4;
        float4 v0 = __ldcs(reinterpret_cast<const float4*>(x + row_base + ebase));
        float4 v1 = __ldcs(reinterpret_cast<const float4*>(x + row_base + ebase + 32));

        // 8-elem in-register tree
        float mn = fminf(fminf(fminf(v0.x, v0.y), fminf(v0.z, v0.w)),
                         fminf(fminf(v1.x, v1.y), fminf(v1.z, v1.w)));
        float mx = fmaxf(fmaxf(fmaxf(v0.x, v0.y), fmaxf(v0.z, v0.w)),
                         fmaxf(fmaxf(v1.x, v1.y), fmaxf(v1.z, v1.w)));
        // 3-level butterfly within the 8-lane group
        mn = fminf(mn, __shfl_xor_sync(0xffffffffu, mn, 1));
        mx = fmaxf(mx, __shfl_xor_sync(0xffffffffu, mx, 1));
        mn = fminf(mn, __shfl_xor_sync(0xffffffffu, mn, 2));
        mx = fmaxf(mx, __shfl_xor_sync(0xffffffffu, mx, 2));
        mn = fminf(mn, __shfl_xor_sync(0xffffffffu, mn, 4));
        mx = fmaxf(mx, __shfl_xor_sync(0xffffffffu, mx, 4));

        float scale = mx - mn;          // exact fp32 subtract, as reference
        if (k == 0) { bmin_s[qb] = mn; scale_s[qb] = scale; }

        // cell(x) = 512*(x - mn)/(scale + eps) = x*s1 + s2
        float s1 = __fdividef(512.0f, scale + EPSF);   // MUFU.RCP + FMUL
        float s2 = -mn * s1;
        float vr[8];
        *reinterpret_cast<float4*>(vr)     = v0;
        *reinterpret_cast<float4*>(vr + 4) = v1;
        #pragma unroll
        for (int jp = 0; jp < 4; jp++) {
            // element 0 of the pair
            float fc0 = fmaf(vr[2 * jp], s1, s2);
            int   ic0 = (int)fc0;
            u32   tt0 = lutv[ic0];
            u32   lo0 = tt0 & 0xffffu;
            u32   hi0 = tt0 >> 16;
            // rare midpoint fetch as a conditional expression -> @P LDS
            float mid0 = (hi0 != lo0) ? lutm[ic0] : -1e30f;
            u32   t0   = (fc0 > mid0) ? hi0 : lo0;
            // element 1 of the pair
            float fc1 = fmaf(vr[2 * jp + 1], s1, s2);
            int   ic1 = (int)fc1;
            u32   tt1 = lutv[ic1];
            u32   lo1 = tt1 & 0xffffu;
            u32   hi1 = tt1 >> 16;
            float mid1 = (hi1 != lo1) ? lutm[ic1] : -1e30f;
            u32   t1   = (fc1 > mid1) ? hi1 : lo1;
            // one PRMT packs the pair: low half = t0, high half = t1
            stash[i * 4 + jp] = __byte_perm(t0, t1, 0x5410);
        }
    }
    __syncthreads();

    // ---- phase 2: row-level min/max of the 128 block scales ----
    if (warp == 0) {
        float a0 = scale_s[lane];
        float a1 = scale_s[lane + 32];
        float a2 = scale_s[lane + 64];
        float a3 = scale_s[lane + 96];
        float mn = fminf(fminf(a0, a1), fminf(a2, a3));
        float mx = fmaxf(fmaxf(a0, a1), fmaxf(a2, a3));
        #pragma unroll
        for (int o = 16; o >= 1; o >>= 1) {
            mn = fminf(mn, __shfl_xor_sync(0xffffffffu, mn, o));
            mx = fmaxf(mx, __shfl_xor_sync(0xffffffffu, mx, o));
        }
        if (lane == 0) { sm_smin = mn; sm_smax = mx; }
    }
    __syncthreads();

    // ---- phase 3: per-block output constants ----
    if (tid < NB) {
        float smin  = sm_smin, smax = sm_smax;
        float scale = scale_s[tid];
        float bmin  = bmin_s[tid];
        float d     = smax - smin;
        // double quantization of scale (8-bit, round-half-even = rintf)
        float sq    = rintf((scale - smin) / (d + EPSF) * 255.0f);
        float srec  = smin + sq / 255.0f * d;
        // out = (t+1)/2 * srec + bmin == t*a + b
        float a = srec * 0.5f;
        float b = a + bmin;
        qc[tid] = make_float2(a, b);
    }
    __syncthreads();

    // ---- phase 4: dequant from register stash, coalesced streaming store ----
    #pragma unroll
    for (int i = 0; i < 4; i++) {
        const int qb    = warp * 16 + i * 4 + g;
        const int ebase = qb * BS + k * 4;
        float2 ab = qc[qb];
        u32 w0 = stash[i * 4 + 0];
        u32 w1 = stash[i * 4 + 1];
        u32 w2 = stash[i * 4 + 2];
        u32 w3 = stash[i * 4 + 3];
        __half2 h0 = *reinterpret_cast<__half2*>(&w0);
        __half2 h1 = *reinterpret_cast<__half2*>(&w1);
        __half2 h2 = *reinterpret_cast<__half2*>(&w2);
        __half2 h3 = *reinterpret_cast<__half2*>(&w3);
        float4 o0, o1;
        o0.x = fmaf(__low2float(h0),  ab.x, ab.y);
        o0.y = fmaf(__high2float(h0), ab.x, ab.y);
        o0.z = fmaf(__low2float(h1),  ab.x, ab.y);
        o0.w = fmaf(__high2float(h1), ab.x, ab.y);
        o1.x = fmaf(__low2float(h2),  ab.x, ab.y);
        o1.y = fmaf(__high2float(h2), ab.x, ab.y);
        o1.z = fmaf(__low2float(h3),  ab.x, ab.y);
        o1.w = fmaf(__high2float(h3), ab.x, ab.y);
        __stcs(reinterpret_cast<float4*>(out + row_base + ebase),      o0);
        __stcs(reinterpret_cast<float4*>(out + row_base + ebase + 32), o1);
    }
}

extern "C" void kernel_launch(void* const* d_in, const int* in_sizes, int n_in,
                              void* d_out, int out_size)
{
    const float* x = (const float*)d_in[0];
    float* out = (float*)d_out;
    int rows = in_sizes[0] / COLS;   // 2048
    nf4_kernel<<<rows, NTHREADS>>>(x, out);
}